// round 1
// baseline (speedup 1.0000x reference)
#include <cuda_runtime.h>
#include <math.h>

#define NN   32
#define CC   64
#define TD   256
#define VV   25
#define ICC  16
#define NSS  3
#define TV   (TD*VV)      // 6400
#define CTV  (CC*TV)      // 409600
#define EPSB 1e-5f
#define TB   4            // t-chunk for tcn kernel

// ---------------- scratch (device globals; no allocation) ----------------
__device__ float g_a  [NSS*NN*ICC*TV];   // [s][n][ic][t][v]
__device__ float g_b  [NSS*NN*ICC*TV];
__device__ float g_att[NSS*NN*VV*VV];    // [s][n][v][w]
__device__ float g_gcn[NN*CTV];          // gcn_out
__device__ float g_msg[NN*CTV];          // tcn output (msg)

// ---------------- kernel 1: a = conv_a(h), b = conv_b(h), all 3 subsets ----------------
__global__ void k_ab(const float* __restrict__ hid,
                     const float* __restrict__ caw, const float* __restrict__ cab,
                     const float* __restrict__ cbw, const float* __restrict__ cbb) {
    __shared__ float s_caw[NSS*ICC*CC], s_cbw[NSS*ICC*CC];
    __shared__ float s_cab[NSS*ICC],    s_cbb[NSS*ICC];
    for (int i = threadIdx.x; i < NSS*ICC*CC; i += blockDim.x) { s_caw[i] = caw[i]; s_cbw[i] = cbw[i]; }
    for (int i = threadIdx.x; i < NSS*ICC;    i += blockDim.x) { s_cab[i] = cab[i]; s_cbb[i] = cbb[i]; }
    __syncthreads();

    int p = blockIdx.x * blockDim.x + threadIdx.x;   // pixel over NN*TV (exact)
    int n = p / TV, r = p % TV;
    const float* hp = hid + (size_t)n * CTV + r;
    float h[CC];
    #pragma unroll
    for (int c = 0; c < CC; c++) h[c] = hp[c * TV];

    for (int s = 0; s < NSS; s++) {
        for (int o = 0; o < ICC; o++) {
            const float* wa = &s_caw[(s*ICC + o) * CC];
            const float* wb = &s_cbw[(s*ICC + o) * CC];
            float aA = s_cab[s*ICC + o], aB = s_cbb[s*ICC + o];
            #pragma unroll
            for (int c = 0; c < CC; c++) { aA += h[c] * wa[c]; aB += h[c] * wb[c]; }
            size_t oi = ((size_t)(s*NN + n) * ICC + o) * TV + r;
            g_a[oi] = aA; g_b[oi] = aB;
        }
    }
}

// ---------------- kernel 2: attention logits + softmax(axis=v) + Aeff ----------------
__global__ void k_att(const float* __restrict__ A, const float* __restrict__ PA) {
    int sn = blockIdx.x;                 // 0 .. NSS*NN-1
    int s = sn / NN;
    __shared__ float sa[64*VV], sb[64*VV], slog[VV*VV];
    const float* ap = g_a + (size_t)sn * (ICC*TV);
    const float* bp = g_b + (size_t)sn * (ICC*TV);
    int tid = threadIdx.x;
    float acc[3] = {0.f, 0.f, 0.f};

    for (int kt = 0; kt < ICC*TD; kt += 64) {
        __syncthreads();
        for (int i = tid; i < 64*VV; i += 256) { sa[i] = ap[kt*VV + i]; sb[i] = bp[kt*VV + i]; }
        __syncthreads();
        #pragma unroll
        for (int j = 0; j < 3; j++) {
            int idx = tid + j*256;
            if (idx < VV*VV) {
                int v = idx / VV, w = idx % VV;
                float a0 = 0.f;
                #pragma unroll
                for (int kk = 0; kk < 64; kk++) a0 += sa[kk*VV + v] * sb[kk*VV + w];
                acc[j] += a0;
            }
        }
    }
    __syncthreads();
    const float scale = 1.0f / (ICC * TD);
    #pragma unroll
    for (int j = 0; j < 3; j++) { int idx = tid + j*256; if (idx < VV*VV) slog[idx] = acc[j] * scale; }
    __syncthreads();

    if (tid < VV) {                       // column softmax over v, per w
        int w = tid;
        float mx = -1e30f;
        for (int v = 0; v < VV; v++) mx = fmaxf(mx, slog[v*VV + w]);
        float e[VV], sum = 0.f;
        for (int v = 0; v < VV; v++) { e[v] = expf(slog[v*VV + w] - mx); sum += e[v]; }
        float inv = 1.0f / sum;
        for (int v = 0; v < VV; v++) {
            int ai = (s*VV + v)*VV + w;
            g_att[((size_t)sn*VV + v)*VV + w] = e[v]*inv + A[ai] + PA[ai];
        }
    }
}

// ---------------- kernel 3: z = h@att, y += conv_d(z); BN + residual + relu -> gcn ----------------
__global__ void k_gcn(const float* __restrict__ hid,
                      const float* __restrict__ cdw, const float* __restrict__ cdb,
                      const float* __restrict__ gg, const float* __restrict__ gb,
                      const float* __restrict__ gm, const float* __restrict__ gv) {
    int bid = blockIdx.x;
    int n = bid / TD, t = bid % TD;
    __shared__ float sh[CC*VV], sz[CC*VV], scdw[CC*CC], satt[VV*VV];
    int tid = threadIdx.x;

    const float* hp = hid + (size_t)n * CTV + t * VV;
    for (int i = tid; i < CC*VV; i += 256) { int c = i / VV, v = i % VV; sh[i] = hp[c*TV + v]; }

    float y[7];
    #pragma unroll
    for (int j = 0; j < 7; j++) y[j] = 0.f;

    for (int s = 0; s < NSS; s++) {
        __syncthreads();
        for (int i = tid; i < CC*CC; i += 256) scdw[i] = cdw[s*CC*CC + i];
        for (int i = tid; i < VV*VV; i += 256) satt[i] = g_att[((size_t)s*NN + n)*VV*VV + i];
        __syncthreads();
        #pragma unroll
        for (int j = 0; j < 7; j++) {
            int idx = tid + j*256;
            if (idx < CC*VV) {
                int c = idx / VV, w = idx % VV;
                float z0 = 0.f;
                #pragma unroll
                for (int v = 0; v < VV; v++) z0 += sh[c*VV + v] * satt[v*VV + w];
                sz[idx] = z0;
            }
        }
        __syncthreads();
        #pragma unroll
        for (int j = 0; j < 7; j++) {
            int idx = tid + j*256;
            if (idx < CC*VV) {
                int o = idx / VV, w = idx % VV;
                float a0 = __ldg(&cdb[s*CC + o]);
                #pragma unroll
                for (int c = 0; c < CC; c++) a0 += scdw[o*CC + c] * sz[c*VV + w];
                y[j] += a0;
            }
        }
    }
    __syncthreads();
    #pragma unroll
    for (int j = 0; j < 7; j++) {
        int idx = tid + j*256;
        if (idx < CC*VV) {
            int o = idx / VV, w = idx % VV;
            float sc = __ldg(&gg[o]) * rsqrtf(__ldg(&gv[o]) + EPSB);
            float val = (y[j] - __ldg(&gm[o])) * sc + __ldg(&gb[o]) + sh[idx];
            g_gcn[(size_t)n*CTV + o*TV + t*VV + w] = fmaxf(val, 0.f);
        }
    }
}

// ---------------- kernel 4: tcn 9-tap conv (pad 4) + BN + residual + relu -> msg ----------------
__global__ void k_tcn(const float* __restrict__ hid,
                      const float* __restrict__ tw, const float* __restrict__ tcb,
                      const float* __restrict__ bg, const float* __restrict__ bb,
                      const float* __restrict__ bm, const float* __restrict__ bv) {
    int bid = blockIdx.x;
    int n  = bid / (TD / TB);
    int t0 = (bid % (TD / TB)) * TB;
    __shared__ float slab[32 * (TB+8) * VV];   // [c(32)][tt(12)][v(25)]
    __shared__ float wt[CC * 32];              // [o][c]
    int tid = threadIdx.x;

    // precompute per-output decomposition (6400 outputs, exactly 25/thread)
    int ob[25], basb[25], ttb[25];
    #pragma unroll
    for (int j = 0; j < 25; j++) {
        int idx = tid + j*256;
        ob[j]  = idx / (TB*VV);
        int rr = idx % (TB*VV);
        ttb[j] = rr / VV;
        basb[j] = rr;                          // tt*25 + v
    }

    float acc[25];
    #pragma unroll
    for (int j = 0; j < 25; j++) acc[j] = 0.f;

    for (int half = 0; half < 2; half++) {
        int c0 = half * 32;
        __syncthreads();
        for (int i = tid; i < 32*(TB+8)*VV; i += 256) {
            int c = i / ((TB+8)*VV);
            int rr = i % ((TB+8)*VV);
            int tt = rr / VV, v = rr % VV;
            int tau = t0 + tt - 4;
            slab[i] = (tau >= 0 && tau < TD)
                    ? g_gcn[(size_t)n*CTV + (c0+c)*TV + tau*VV + v] : 0.f;
        }
        for (int dt = 0; dt < 9; dt++) {
            __syncthreads();
            for (int i = tid; i < CC*32; i += 256) {
                int o = i / 32, c = i % 32;
                wt[i] = tw[(o*CC + (c0+c))*9 + dt];
            }
            __syncthreads();
            #pragma unroll
            for (int j = 0; j < 25; j++) {
                int sbase = basb[j] + dt*VV;
                float a0 = 0.f;
                #pragma unroll
                for (int c = 0; c < 32; c++) a0 += wt[ob[j]*32 + c] * slab[c*((TB+8)*VV) + sbase];
                acc[j] += a0;
            }
        }
    }
    #pragma unroll
    for (int j = 0; j < 25; j++) {
        int o = ob[j];
        int v = basb[j] - ttb[j]*VV;
        float val = acc[j] + __ldg(&tcb[o]);
        float sc = __ldg(&bg[o]) * rsqrtf(__ldg(&bv[o]) + EPSB);
        val = (val - __ldg(&bm[o])) * sc + __ldg(&bb[o]);
        size_t oi = (size_t)n*CTV + o*TV + (t0+ttb[j])*VV + v;
        val += hid[oi];
        g_msg[oi] = fmaxf(val, 0.f);
    }
}

// ---------------- kernel 5: fused GRU cell ----------------
__global__ void k_gru(const float* __restrict__ feat, const float* __restrict__ hid,
                      const float* __restrict__ W_ir, const float* __restrict__ W_ii,
                      const float* __restrict__ W_in, const float* __restrict__ W_hr,
                      const float* __restrict__ W_hi, const float* __restrict__ W_hh,
                      const float* __restrict__ b_ir, const float* __restrict__ b_ii,
                      const float* __restrict__ b_in, float* __restrict__ out) {
    int bid = blockIdx.x;
    int n = bid / TD, t = bid % TD;
    __shared__ float sx[CC*VV], sm[CC*VV], sWa[CC*CC], sWb[CC*CC];
    int tid = threadIdx.x;

    const float* fp = feat  + (size_t)n*CTV + t*VV;
    const float* mp = g_msg + (size_t)n*CTV + t*VV;
    for (int i = tid; i < CC*VV; i += 256) { int c = i/VV, v = i%VV; sx[i] = fp[c*TV + v]; sm[i] = mp[c*TV + v]; }

    float rg[7], zg[7], ng[7];

    // r gate
    __syncthreads();
    for (int i = tid; i < CC*CC; i += 256) { sWa[i] = W_ir[i]; sWb[i] = W_hr[i]; }
    __syncthreads();
    #pragma unroll
    for (int j = 0; j < 7; j++) {
        int idx = tid + j*256;
        if (idx < CC*VV) {
            int o = idx / VV, v = idx % VV;
            float a0 = __ldg(&b_ir[o]), a1 = 0.f;
            #pragma unroll
            for (int c = 0; c < CC; c++) { a0 += sWa[o*CC+c]*sx[c*VV+v]; a1 += sWb[o*CC+c]*sm[c*VV+v]; }
            rg[j] = 1.0f / (1.0f + expf(-(a0 + a1)));
        }
    }
    // z gate
    __syncthreads();
    for (int i = tid; i < CC*CC; i += 256) { sWa[i] = W_ii[i]; sWb[i] = W_hi[i]; }
    __syncthreads();
    #pragma unroll
    for (int j = 0; j < 7; j++) {
        int idx = tid + j*256;
        if (idx < CC*VV) {
            int o = idx / VV, v = idx % VV;
            float a0 = __ldg(&b_ii[o]), a1 = 0.f;
            #pragma unroll
            for (int c = 0; c < CC; c++) { a0 += sWa[o*CC+c]*sx[c*VV+v]; a1 += sWb[o*CC+c]*sm[c*VV+v]; }
            zg[j] = 1.0f / (1.0f + expf(-(a0 + a1)));
        }
    }
    // n candidate
    __syncthreads();
    for (int i = tid; i < CC*CC; i += 256) { sWa[i] = W_in[i]; sWb[i] = W_hh[i]; }
    __syncthreads();
    #pragma unroll
    for (int j = 0; j < 7; j++) {
        int idx = tid + j*256;
        if (idx < CC*VV) {
            int o = idx / VV, v = idx % VV;
            float a0 = __ldg(&b_in[o]), a1 = 0.f;
            #pragma unroll
            for (int c = 0; c < CC; c++) { a0 += sWa[o*CC+c]*sx[c*VV+v]; a1 += sWb[o*CC+c]*sm[c*VV+v]; }
            ng[j] = tanhf(a0 + rg[j]*a1);
        }
    }
    // output
    #pragma unroll
    for (int j = 0; j < 7; j++) {
        int idx = tid + j*256;
        if (idx < CC*VV) {
            int o = idx / VV, v = idx % VV;
            size_t oi = (size_t)n*CTV + o*TV + t*VV + v;
            float hv = hid[oi];
            out[oi] = (1.0f - zg[j]) * ng[j] + zg[j] * hv;
        }
    }
}

// ---------------- launcher ----------------
extern "C" void kernel_launch(void* const* d_in, const int* in_sizes, int n_in,
                              void* d_out, int out_size) {
    const float* feature = (const float*)d_in[0];
    const float* hidden  = (const float*)d_in[1];
    const float* A   = (const float*)d_in[2];
    const float* PA  = (const float*)d_in[3];
    const float* caw = (const float*)d_in[4];
    const float* cab = (const float*)d_in[5];
    const float* cbw = (const float*)d_in[6];
    const float* cbb = (const float*)d_in[7];
    const float* cdw = (const float*)d_in[8];
    const float* cdb = (const float*)d_in[9];
    const float* gg  = (const float*)d_in[10];
    const float* gb  = (const float*)d_in[11];
    const float* gm  = (const float*)d_in[12];
    const float* gv  = (const float*)d_in[13];
    const float* tw  = (const float*)d_in[14];
    const float* tcb = (const float*)d_in[15];
    const float* bg  = (const float*)d_in[16];
    const float* bb  = (const float*)d_in[17];
    const float* bm  = (const float*)d_in[18];
    const float* bv  = (const float*)d_in[19];

    // GRU weight ordering: metadata may follow setup_inputs dict order
    // (W_ir,W_ii,W_in,W_hr,W_hi,W_hh,b_ir,b_ii,b_in) or reference-signature order
    // (W_ir,b_ir,W_ii,b_ii,W_in,b_in,W_hr,W_hi,W_hh). Detect via element counts.
    const float *W_ir, *W_ii, *W_in, *W_hr, *W_hi, *W_hh, *b_ir, *b_ii, *b_in;
    if (in_sizes[21] == 64) {   // signature order: index 21 is b_ir (64 elems)
        W_ir = (const float*)d_in[20]; b_ir = (const float*)d_in[21];
        W_ii = (const float*)d_in[22]; b_ii = (const float*)d_in[23];
        W_in = (const float*)d_in[24]; b_in = (const float*)d_in[25];
        W_hr = (const float*)d_in[26]; W_hi = (const float*)d_in[27];
        W_hh = (const float*)d_in[28];
    } else {                    // dict order
        W_ir = (const float*)d_in[20]; W_ii = (const float*)d_in[21];
        W_in = (const float*)d_in[22]; W_hr = (const float*)d_in[23];
        W_hi = (const float*)d_in[24]; W_hh = (const float*)d_in[25];
        b_ir = (const float*)d_in[26]; b_ii = (const float*)d_in[27];
        b_in = (const float*)d_in[28];
    }

    k_ab <<<NN*TV/128, 128>>>(hidden, caw, cab, cbw, cbb);
    k_att<<<NSS*NN,    256>>>(A, PA);
    k_gcn<<<NN*TD,     256>>>(hidden, cdw, cdb, gg, gb, gm, gv);
    k_tcn<<<NN*(TD/TB),256>>>(hidden, tw, tcb, bg, bb, bm, bv);
    k_gru<<<NN*TD,     256>>>(feature, hidden, W_ir, W_ii, W_in, W_hr, W_hi, W_hh,
                              b_ir, b_ii, b_in, (float*)d_out);
}

// round 2
// speedup vs baseline: 2.7831x; 2.7831x over previous
#include <cuda_runtime.h>
#include <math.h>

#define NN   32
#define CC   64
#define TD   256
#define VV   25
#define ICC  16
#define NSS  3
#define TV   (TD*VV)      // 6400
#define CTV  (CC*TV)      // 409600
#define EPSB 1e-5f

// ---------------- scratch (device globals; no allocation) ----------------
__device__ float g_a  [NSS*NN*ICC*TV];        // [s][n][ic][r]
__device__ float g_b  [NSS*NN*ICC*TV];
__device__ float g_att[NSS*NN*VV*VV];         // [s][n][v][w]
__device__ float g_u  [NSS*NN*TV*CC];         // [s][n][r][o]  (Wd@h, transposed)
__device__ float g_gcn[NN*CTV];               // gcn_out [n][c][r]
__device__ float g_msg[NN*CTV];               // tcn output (msg)
// transposed weights
__device__ float g_wa [CC*96];                // [c][o] for conv_a (o = s*16+ic)
__device__ float g_wb [CC*96];
__device__ float g_wd [NSS*CC*CC];            // [s][c][o]
__device__ float g_wt [9*CC*CC];              // [dt][c][o]
__device__ float g_wg [6*CC*CC];              // [ir,hr,ii,hi,in,hh][c][o]

// ---------------- weight repack ----------------
__global__ void k_repack(const float* __restrict__ caw, const float* __restrict__ cbw,
                         const float* __restrict__ cdw, const float* __restrict__ tw,
                         const float* __restrict__ Wir, const float* __restrict__ Whr,
                         const float* __restrict__ Wii, const float* __restrict__ Whi,
                         const float* __restrict__ Win, const float* __restrict__ Whh) {
    int i = blockIdx.x * blockDim.x + threadIdx.x;
    if (i < 96*64)   { int o = i/64, c = i%64; g_wa[c*96+o] = caw[i]; g_wb[c*96+o] = cbw[i]; }
    if (i < 3*64*64) { int s = i/4096, r = i%4096; int o = r/64, c = r%64; g_wd[(s*64+c)*64+o] = cdw[i]; }
    if (i < 64*64*9) { int oc = i/9, dt = i%9; int o = oc/64, c = oc%64; g_wt[(dt*64+c)*64+o] = tw[i]; }
    if (i < 64*64)   { int o = i/64, c = i%64; int t_ = c*64+o;
        g_wg[0*4096+t_]=Wir[i]; g_wg[1*4096+t_]=Whr[i]; g_wg[2*4096+t_]=Wii[i];
        g_wg[3*4096+t_]=Whi[i]; g_wg[4*4096+t_]=Win[i]; g_wg[5*4096+t_]=Whh[i]; }
}

// ---------------- shared GEMM chunk helpers ----------------
// sx: [16][128] data tile, sw: [16][64] weight tile (already [c][o])
__device__ __forceinline__ void fma_chunk64(const float* sx, const float* sw,
                                            float* acc, int og, int pg) {
    #pragma unroll
    for (int kk = 0; kk < 16; kk++) {
        float4 w0 = *(const float4*)&sw[kk*64 + og*8];
        float4 w1 = *(const float4*)&sw[kk*64 + og*8 + 4];
        float4 x4 = *(const float4*)&sx[kk*128 + pg*4];
        float wv[8] = {w0.x,w0.y,w0.z,w0.w,w1.x,w1.y,w1.z,w1.w};
        float xv[4] = {x4.x,x4.y,x4.z,x4.w};
        #pragma unroll
        for (int i = 0; i < 8; i++)
            #pragma unroll
            for (int j = 0; j < 4; j++) acc[i*4+j] += wv[i]*xv[j];
    }
}

// K=64 GEMM accumulate: data gx (already offset to [c][p0..]), weight wt [c][64]
__device__ __forceinline__ void gemm_k64(const float* __restrict__ gx,
                                         const float* __restrict__ wt,
                                         float* sx, float* sw, float* acc,
                                         int p0, int og, int pg, int tid) {
    for (int kc = 0; kc < 4; kc++) {
        __syncthreads();
        for (int i4 = tid; i4 < 512; i4 += 256) {
            int kk = i4 >> 5, p4 = i4 & 31;
            ((float4*)sx)[kk*32 + p4] = *(const float4*)&gx[(kc*16+kk)*TV + p0 + p4*4];
        }
        ((float4*)sw)[tid] = ((const float4*)wt)[kc*256 + tid];
        __syncthreads();
        fma_chunk64(sx, sw, acc, og, pg);
    }
}

// ---------------- kernel 1: a/b projections (M=192 fused) ----------------
__global__ __launch_bounds__(384) void k_ab(const float* __restrict__ hid,
                     const float* __restrict__ cab, const float* __restrict__ cbb) {
    __shared__ float sx[16*128], swa[16*96], swb[16*96];
    int tid = threadIdx.x;
    int og = tid >> 5, pg = tid & 31;           // og 0..11
    int n = blockIdx.x / 50, p0 = (blockIdx.x % 50) * 128;
    const float* hp = hid + (size_t)n * CTV;

    float accA[32], accB[32];
    #pragma unroll
    for (int i = 0; i < 32; i++) { accA[i] = 0.f; accB[i] = 0.f; }

    for (int kc = 0; kc < 4; kc++) {
        __syncthreads();
        for (int i4 = tid; i4 < 512; i4 += 384) {
            int kk = i4 >> 5, p4 = i4 & 31;
            ((float4*)sx)[kk*32 + p4] = *(const float4*)&hp[(kc*16+kk)*TV + p0 + p4*4];
        }
        ((float4*)swa)[tid] = ((const float4*)g_wa)[kc*384 + tid];
        ((float4*)swb)[tid] = ((const float4*)g_wb)[kc*384 + tid];
        __syncthreads();
        #pragma unroll
        for (int kk = 0; kk < 16; kk++) {
            float4 wa0 = *(const float4*)&swa[kk*96 + og*8];
            float4 wa1 = *(const float4*)&swa[kk*96 + og*8 + 4];
            float4 wb0 = *(const float4*)&swb[kk*96 + og*8];
            float4 wb1 = *(const float4*)&swb[kk*96 + og*8 + 4];
            float4 x4  = *(const float4*)&sx[kk*128 + pg*4];
            float wav[8] = {wa0.x,wa0.y,wa0.z,wa0.w,wa1.x,wa1.y,wa1.z,wa1.w};
            float wbv[8] = {wb0.x,wb0.y,wb0.z,wb0.w,wb1.x,wb1.y,wb1.z,wb1.w};
            float xv[4]  = {x4.x,x4.y,x4.z,x4.w};
            #pragma unroll
            for (int i = 0; i < 8; i++)
                #pragma unroll
                for (int j = 0; j < 4; j++) {
                    accA[i*4+j] += wav[i]*xv[j];
                    accB[i*4+j] += wbv[i]*xv[j];
                }
        }
    }
    #pragma unroll
    for (int i = 0; i < 8; i++) {
        int o = og*8 + i;
        int s = o >> 4, ic = o & 15;
        size_t base = ((size_t)(s*NN + n)*ICC + ic)*TV + p0 + pg*4;
        float ba = __ldg(&cab[o]), bb = __ldg(&cbb[o]);
        float4 va = {accA[i*4]+ba, accA[i*4+1]+ba, accA[i*4+2]+ba, accA[i*4+3]+ba};
        float4 vb = {accB[i*4]+bb, accB[i*4+1]+bb, accB[i*4+2]+bb, accB[i*4+3]+bb};
        *(float4*)&g_a[base] = va;
        *(float4*)&g_b[base] = vb;
    }
}

// ---------------- kernel 2: attention logits + softmax + Aeff ----------------
__global__ void k_att(const float* __restrict__ A, const float* __restrict__ PA) {
    int sn = blockIdx.x;                 // 0 .. NSS*NN-1
    int s = sn / NN;
    __shared__ float sa[64*VV], sb[64*VV], slog[VV*VV];
    const float* ap = g_a + (size_t)sn * (ICC*TV);
    const float* bp = g_b + (size_t)sn * (ICC*TV);
    int tid = threadIdx.x;
    float acc[3] = {0.f, 0.f, 0.f};

    for (int kt = 0; kt < ICC*TD; kt += 64) {
        __syncthreads();
        for (int i = tid; i < 64*VV; i += 256) { sa[i] = ap[kt*VV + i]; sb[i] = bp[kt*VV + i]; }
        __syncthreads();
        #pragma unroll
        for (int j = 0; j < 3; j++) {
            int idx = tid + j*256;
            if (idx < VV*VV) {
                int v = idx / VV, w = idx % VV;
                float a0 = 0.f;
                #pragma unroll
                for (int kk = 0; kk < 64; kk++) a0 += sa[kk*VV + v] * sb[kk*VV + w];
                acc[j] += a0;
            }
        }
    }
    __syncthreads();
    const float scale = 1.0f / (ICC * TD);
    #pragma unroll
    for (int j = 0; j < 3; j++) { int idx = tid + j*256; if (idx < VV*VV) slog[idx] = acc[j] * scale; }
    __syncthreads();

    if (tid < VV) {
        int w = tid;
        float mx = -1e30f;
        for (int v = 0; v < VV; v++) mx = fmaxf(mx, slog[v*VV + w]);
        float e[VV], sum = 0.f;
        for (int v = 0; v < VV; v++) { e[v] = expf(slog[v*VV + w] - mx); sum += e[v]; }
        float inv = 1.0f / sum;
        for (int v = 0; v < VV; v++) {
            int ai = (s*VV + v)*VV + w;
            g_att[((size_t)sn*VV + v)*VV + w] = e[v]*inv + A[ai] + PA[ai];
        }
    }
}

// ---------------- kernel 3a: u_s = Wd_s @ h  (stored [s][n][r][o]) ----------------
__global__ __launch_bounds__(256) void k_u(const float* __restrict__ hid) {
    __shared__ float sx[16*128], sw[16*64];
    int tid = threadIdx.x;
    int og = tid >> 5, pg = tid & 31;
    int n = blockIdx.x / 50, p0 = (blockIdx.x % 50) * 128;
    int s = blockIdx.y;
    const float* hp = hid + (size_t)n * CTV;

    float acc[32];
    #pragma unroll
    for (int i = 0; i < 32; i++) acc[i] = 0.f;
    gemm_k64(hp, g_wd + s*CC*CC, sx, sw, acc, p0, og, pg, tid);

    float* up = g_u + ((size_t)(s*NN + n)*TV) * CC;
    #pragma unroll
    for (int j = 0; j < 4; j++) {
        int p = p0 + pg*4 + j;
        float4 v0 = {acc[0*4+j], acc[1*4+j], acc[2*4+j], acc[3*4+j]};
        float4 v1 = {acc[4*4+j], acc[5*4+j], acc[6*4+j], acc[7*4+j]};
        *(float4*)&up[(size_t)p*CC + og*8]     = v0;
        *(float4*)&up[(size_t)p*CC + og*8 + 4] = v1;
    }
}

// ---------------- kernel 3b: y = sum_s u_s@att_s + bias; BN + residual + relu ----------------
__global__ __launch_bounds__(256) void k_gcn2(const float* __restrict__ hid,
                       const float* __restrict__ cdb,
                       const float* __restrict__ gg, const float* __restrict__ gb,
                       const float* __restrict__ gm, const float* __restrict__ gv) {
    __shared__ float su[NSS*VV*CC];      // [(s*25+v)*64 + o]
    __shared__ float satt[NSS*VV*VV];
    int tid = threadIdx.x;
    int n = blockIdx.x / TD, t = blockIdx.x % TD;

    for (int i4 = tid; i4 < 1200; i4 += 256) {
        int s = i4 / 400, j = i4 % 400;
        ((float4*)su)[i4] = ((const float4*)(g_u + ((size_t)(s*NN + n)*TV + t*VV)*CC))[j];
    }
    for (int i = tid; i < NSS*VV*VV; i += 256) {
        int s = i / 625, j = i % 625;
        satt[i] = g_att[(size_t)(s*NN + n)*625 + j];
    }
    __syncthreads();

    if (tid < 200) {
        int og = tid / VV, w = tid % VV;
        float acc[8];
        #pragma unroll
        for (int i = 0; i < 8; i++) acc[i] = 0.f;
        for (int s = 0; s < NSS; s++) {
            #pragma unroll
            for (int v = 0; v < VV; v++) {
                float4 u0 = *(const float4*)&su[(s*VV+v)*CC + og*8];
                float4 u1 = *(const float4*)&su[(s*VV+v)*CC + og*8 + 4];
                float a = satt[(s*VV+v)*VV + w];
                acc[0] += u0.x*a; acc[1] += u0.y*a; acc[2] += u0.z*a; acc[3] += u0.w*a;
                acc[4] += u1.x*a; acc[5] += u1.y*a; acc[6] += u1.z*a; acc[7] += u1.w*a;
            }
        }
        #pragma unroll
        for (int i = 0; i < 8; i++) {
            int o = og*8 + i;
            float bias = __ldg(&cdb[o]) + __ldg(&cdb[64+o]) + __ldg(&cdb[128+o]);
            float sc = __ldg(&gg[o]) * rsqrtf(__ldg(&gv[o]) + EPSB);
            size_t oi = (size_t)n*CTV + (size_t)o*TV + t*VV + w;
            float val = (acc[i] + bias - __ldg(&gm[o])) * sc + __ldg(&gb[o]) + hid[oi];
            g_gcn[oi] = fmaxf(val, 0.f);
        }
    }
}

// ---------------- kernel 4: tcn 9-tap conv + BN + residual + relu ----------------
__global__ __launch_bounds__(256) void k_tcn(const float* __restrict__ hid,
                      const float* __restrict__ tcb,
                      const float* __restrict__ bg, const float* __restrict__ bb,
                      const float* __restrict__ bm, const float* __restrict__ bv) {
    __shared__ float sx[16*128], sw[16*64];
    int tid = threadIdx.x;
    int og = tid >> 5, pg = tid & 31;
    int n = blockIdx.x / 50, p0 = (blockIdx.x % 50) * 128;
    const float* gp = g_gcn + (size_t)n * CTV;

    float acc[32];
    #pragma unroll
    for (int i = 0; i < 32; i++) acc[i] = 0.f;

    for (int dt = 0; dt < 9; dt++) {
        int shift = 25*(dt-4);
        for (int kc = 0; kc < 4; kc++) {
            __syncthreads();
            #pragma unroll
            for (int ii = 0; ii < 8; ii++) {
                int i = tid + ii*256;
                int kk = i >> 7, p = i & 127;
                int r = p0 + p + shift;
                sx[i] = (r >= 0 && r < TV) ? gp[(size_t)(kc*16+kk)*TV + r] : 0.f;
            }
            ((float4*)sw)[tid] = ((const float4*)(g_wt + dt*CC*CC))[kc*256 + tid];
            __syncthreads();
            fma_chunk64(sx, sw, acc, og, pg);
        }
    }
    #pragma unroll
    for (int i = 0; i < 8; i++) {
        int o = og*8 + i;
        float sc = __ldg(&bg[o]) * rsqrtf(__ldg(&bv[o]) + EPSB);
        float bias = __ldg(&tcb[o]), mean = __ldg(&bm[o]), beta = __ldg(&bb[o]);
        size_t base = (size_t)n*CTV + (size_t)o*TV + p0 + pg*4;
        float4 hres = *(const float4*)&hid[base];
        float4 v;
        v.x = fmaxf((acc[i*4+0]+bias-mean)*sc + beta + hres.x, 0.f);
        v.y = fmaxf((acc[i*4+1]+bias-mean)*sc + beta + hres.y, 0.f);
        v.z = fmaxf((acc[i*4+2]+bias-mean)*sc + beta + hres.z, 0.f);
        v.w = fmaxf((acc[i*4+3]+bias-mean)*sc + beta + hres.w, 0.f);
        *(float4*)&g_msg[base] = v;
    }
}

// ---------------- kernel 5: fused GRU cell ----------------
__global__ __launch_bounds__(256) void k_gru(const float* __restrict__ feat,
                      const float* __restrict__ hid,
                      const float* __restrict__ b_ir, const float* __restrict__ b_ii,
                      const float* __restrict__ b_in, float* __restrict__ out) {
    __shared__ float sx[16*128], sw[16*64];
    int tid = threadIdx.x;
    int og = tid >> 5, pg = tid & 31;
    int n = blockIdx.x / 50, p0 = (blockIdx.x % 50) * 128;
    const float* xp = feat  + (size_t)n * CTV;
    const float* mp = g_msg + (size_t)n * CTV;

    float A[32], B[32], Cc[32];
    #pragma unroll
    for (int i = 0; i < 32; i++) { A[i] = 0.f; B[i] = 0.f; Cc[i] = 0.f; }

    // A = Whh @ m
    gemm_k64(mp, g_wg + 5*4096, sx, sw, A, p0, og, pg, tid);
    // B = Wir @ x + Whr @ m  -> r
    gemm_k64(xp, g_wg + 0*4096, sx, sw, B, p0, og, pg, tid);
    gemm_k64(mp, g_wg + 1*4096, sx, sw, B, p0, og, pg, tid);
    #pragma unroll
    for (int i = 0; i < 8; i++) {
        float bi = __ldg(&b_ir[og*8+i]);
        #pragma unroll
        for (int j = 0; j < 4; j++) B[i*4+j] = 1.0f/(1.0f + __expf(-(B[i*4+j] + bi)));
    }
    // Cc = Win @ x -> n = tanh(Cc + b_in + r*A)
    gemm_k64(xp, g_wg + 4*4096, sx, sw, Cc, p0, og, pg, tid);
    #pragma unroll
    for (int i = 0; i < 8; i++) {
        float bi = __ldg(&b_in[og*8+i]);
        #pragma unroll
        for (int j = 0; j < 4; j++) {
            float t_ = Cc[i*4+j] + bi + B[i*4+j]*A[i*4+j];
            float e2 = __expf(2.0f*t_);
            Cc[i*4+j] = (e2 - 1.0f)/(e2 + 1.0f);
        }
    }
    // A (reuse) = Wii @ x + Whi @ m -> z
    #pragma unroll
    for (int i = 0; i < 32; i++) A[i] = 0.f;
    gemm_k64(xp, g_wg + 2*4096, sx, sw, A, p0, og, pg, tid);
    gemm_k64(mp, g_wg + 3*4096, sx, sw, A, p0, og, pg, tid);
    #pragma unroll
    for (int i = 0; i < 8; i++) {
        float bi = __ldg(&b_ii[og*8+i]);
        size_t base = (size_t)n*CTV + (size_t)(og*8+i)*TV + p0 + pg*4;
        float4 hres = *(const float4*)&hid[base];
        float hv[4] = {hres.x, hres.y, hres.z, hres.w};
        float4 v;
        float* vp = &v.x;
        #pragma unroll
        for (int j = 0; j < 4; j++) {
            float z = 1.0f/(1.0f + __expf(-(A[i*4+j] + bi)));
            vp[j] = (1.0f - z)*Cc[i*4+j] + z*hv[j];
        }
        *(float4*)&out[base] = v;
    }
}

// ---------------- launcher ----------------
extern "C" void kernel_launch(void* const* d_in, const int* in_sizes, int n_in,
                              void* d_out, int out_size) {
    const float* feature = (const float*)d_in[0];
    const float* hidden  = (const float*)d_in[1];
    const float* A   = (const float*)d_in[2];
    const float* PA  = (const float*)d_in[3];
    const float* caw = (const float*)d_in[4];
    const float* cab = (const float*)d_in[5];
    const float* cbw = (const float*)d_in[6];
    const float* cbb = (const float*)d_in[7];
    const float* cdw = (const float*)d_in[8];
    const float* cdb = (const float*)d_in[9];
    const float* gg  = (const float*)d_in[10];
    const float* gb  = (const float*)d_in[11];
    const float* gm  = (const float*)d_in[12];
    const float* gv  = (const float*)d_in[13];
    const float* tw  = (const float*)d_in[14];
    const float* tcb = (const float*)d_in[15];
    const float* bg  = (const float*)d_in[16];
    const float* bb  = (const float*)d_in[17];
    const float* bm  = (const float*)d_in[18];
    const float* bv  = (const float*)d_in[19];

    const float *W_ir, *W_ii, *W_in, *W_hr, *W_hi, *W_hh, *b_ir, *b_ii, *b_in;
    if (in_sizes[21] == 64) {   // signature order
        W_ir = (const float*)d_in[20]; b_ir = (const float*)d_in[21];
        W_ii = (const float*)d_in[22]; b_ii = (const float*)d_in[23];
        W_in = (const float*)d_in[24]; b_in = (const float*)d_in[25];
        W_hr = (const float*)d_in[26]; W_hi = (const float*)d_in[27];
        W_hh = (const float*)d_in[28];
    } else {                    // dict order
        W_ir = (const float*)d_in[20]; W_ii = (const float*)d_in[21];
        W_in = (const float*)d_in[22]; W_hr = (const float*)d_in[23];
        W_hi = (const float*)d_in[24]; W_hh = (const float*)d_in[25];
        b_ir = (const float*)d_in[26]; b_ii = (const float*)d_in[27];
        b_in = (const float*)d_in[28];
    }

    k_repack<<<144, 256>>>(caw, cbw, cdw, tw, W_ir, W_hr, W_ii, W_hi, W_in, W_hh);
    k_ab  <<<1600, 384>>>(hidden, cab, cbb);
    k_att <<<NSS*NN, 256>>>(A, PA);
    k_u   <<<dim3(1600,3), 256>>>(hidden);
    k_gcn2<<<NN*TD, 256>>>(hidden, cdb, gg, gb, gm, gv);
    k_tcn <<<1600, 256>>>(hidden, tcb, bg, bb, bm, bv);
    k_gru <<<1600, 256>>>(feature, hidden, b_ir, b_ii, b_in, (float*)d_out);
}